// round 13
// baseline (speedup 1.0000x reference)
#include <cuda_runtime.h>
#include <cuda_fp16.h>
#include <math.h>
#include <stdint.h>

#define Bn 64
#define Tn 2048
#define Dn 256
#define Un 256

// ---- scratch (device globals, no allocation) ----
__device__ float d_qp[Bn * Un];            // q_proj + W1_b + W2_b
__device__ float d_score[Bn * Tn];         // pre-softmax scores
__device__ float d_maxv[Bn];
__device__ float d_den[Bn];
__device__ float d_part[Bn * 32 * Dn];     // partial context sums
// W2 as fp16, chunk-major, smem-image layout: [8 chunks][256 rows][20 u32]
__device__ __align__(16) uint32_t d_W2h[8 * 256 * 20];

// ================= helpers =================
__device__ __forceinline__ uint32_t smem_u32(const void* p) {
    uint32_t a;
    asm("{ .reg .u64 t; cvta.to.shared.u64 t, %1; cvt.u32.u64 %0, t; }" : "=r"(a) : "l"(p));
    return a;
}
__device__ __forceinline__ void cp_async16(uint32_t dst, const void* src) {
    asm volatile("cp.async.ca.shared.global [%0], [%1], 16;" :: "r"(dst), "l"(src) : "memory");
}
__device__ __forceinline__ void cp_commit() {
    asm volatile("cp.async.commit_group;" ::: "memory");
}
template <int N>
__device__ __forceinline__ void cp_wait() {
    asm volatile("cp.async.wait_group %0;" :: "n"(N) : "memory");
}
__device__ __forceinline__ void mma_f16(float* c, const uint32_t* a, uint32_t b0, uint32_t b1) {
    asm volatile(
        "mma.sync.aligned.m16n8k16.row.col.f32.f16.f16.f32 "
        "{%0,%1,%2,%3}, {%4,%5,%6,%7}, {%8,%9}, {%0,%1,%2,%3};"
        : "+f"(c[0]), "+f"(c[1]), "+f"(c[2]), "+f"(c[3])
        : "r"(a[0]), "r"(a[1]), "r"(a[2]), "r"(a[3]), "r"(b0), "r"(b1));
}
#define LDSM_X4(r0, r1, r2, r3, addr) \
    asm volatile("ldmatrix.sync.aligned.m8n8.x4.shared.b16 {%0,%1,%2,%3}, [%4];" \
                 : "=r"(r0), "=r"(r1), "=r"(r2), "=r"(r3) : "r"(addr))
__device__ __forceinline__ uint32_t pack_h2(float lo, float hi) {
    __half2 h = __floats2half2_rn(lo, hi);   // .x = lo
    return *(uint32_t*)&h;
}
static __device__ __forceinline__ float tanh_fast(float x) {
    float r;
    asm("tanh.approx.f32 %0, %1;" : "=f"(r) : "f"(x));
    return r;
}

// ============================================================
// Kernel 0: prep — qproj (blocks 0..63) + W2h build (blocks 64..95)
// ============================================================
__global__ void prep_kernel(const float* __restrict__ query,
                            const float* __restrict__ W1w,
                            const float* __restrict__ W1b,
                            const float* __restrict__ W2w,
                            const float* __restrict__ W2b) {
    if (blockIdx.x < 64) {
        int b = blockIdx.x, u = threadIdx.x;
        __shared__ float qs[Dn];
        qs[u] = query[b * Dn + u];
        __syncthreads();
        float acc = 0.f;
#pragma unroll 8
        for (int d = 0; d < Dn; d++) acc = fmaf(qs[d], W1w[d * Un + u], acc);
        d_qp[b * Un + u] = acc + W1b[u] + W2b[u];
    } else {
        int id = (blockIdx.x - 64) * 256 + threadIdx.x;   // 0..8191
        int qg = id & 3;
        int urow = (id >> 2) & 255;
        int c = id >> 10;
        uint32_t w[4];
#pragma unroll
        for (int i = 0; i < 4; i++) {
            int q = qg * 4 + i;
            int k = c * 32 + 2 * q;
            w[i] = pack_h2(W2w[(size_t)k * Un + urow], W2w[(size_t)(k + 1) * Un + urow]);
        }
        *(uint4*)&d_W2h[(c * 256 + urow) * 20 + qg * 4] = make_uint4(w[0], w[1], w[2], w[3]);
    }
}

// ============================================================
// Kernel 2: fp16 mma.sync GEMM (128 x 256 x 256) + tanh + dot(Vw)
// 512 threads = 16 warps = 4 M-groups x 4 N-groups, warp tile 32x64.
// A: fp32 LDG -> fp16 pack -> STS. B: direct cp.async of fp16 image.
// Double-buffered, stride-20 u32 rows, ldmatrix fragments.
// ============================================================
#define ST 20                       // uint32 stride per row (16 data + 4 pad)
#define A_ROWS 128
#define A_U32 (A_ROWS * ST)         // 2560 per buffer
#define B_U32 (256 * ST)            // 5120 per buffer
#define SC_SMEM (2 * (A_U32 + B_U32) * 4)   // 61440 B

__global__ __launch_bounds__(512, 1)
void score_kernel(const float* __restrict__ values,
                  const float* __restrict__ Vw,
                  const float* __restrict__ Vb) {
    extern __shared__ __align__(16) uint32_t su[];
    uint32_t* Abuf = su;                 // 2 x A_U32
    uint32_t* Bbuf = su + 2 * A_U32;     // 2 x B_U32
    __shared__ float qs[Un];
    __shared__ float vs[Un];
    __shared__ float sp[A_ROWS * 4];

    const int tid = threadIdx.x;
    const int wid = tid >> 5;
    const int lane = tid & 31;
    const int g = lane >> 2;       // 0..7
    const int tg = lane & 3;       // 0..3
    const int mw = wid >> 2;       // 0..3  (32-row group)
    const int nw = wid & 3;        // 0..3  (64-col group)
    const int r0 = blockIdx.x * A_ROWS;
    const int b = r0 >> 11;

    if (tid < Un) { qs[tid] = d_qp[b * Un + tid]; vs[tid] = Vw[tid]; }

    const int arow = tid >> 3;          // 0..63 base row
    const int kq = tid & 7;             // float4 quad within 32-k chunk

    // ldmatrix lane decomposition
    const int lr = lane & 7;
    const int lh = (lane >> 3) & 1;
    const int lk = (lane >> 4) & 1;

    const uint32_t abase = smem_u32(Abuf);
    const uint32_t bbase = smem_u32(Bbuf);

    uint32_t aoff[2];
#pragma unroll
    for (int i = 0; i < 2; i++)
        aoff[i] = (uint32_t)(((mw * 32 + i * 16 + lr + lh * 8) * ST + lk * 4) * 4);
    uint32_t boff[4];
#pragma unroll
    for (int jp = 0; jp < 4; jp++)
        boff[jp] = (uint32_t)(((nw * 64 + jp * 16 + lr + lk * 8) * ST + lh * 4) * 4);

    float4 pa[2];

    auto ldg_a = [&](int c) {
        const int kc = c * 32;
        const float* agp = values + (size_t)r0 * Dn + kc + kq * 4;
#pragma unroll
        for (int it = 0; it < 2; it++)
            pa[it] = *(const float4*)(agp + (size_t)(arow + it * 64) * Dn);
    };
    auto cp_b = [&](int c, int buf) {
        const uint32_t* src = d_W2h + c * B_U32;
        uint32_t dstb = bbase + (uint32_t)(buf * B_U32 * 4);
        // 1280 16B slots over 512 threads
        cp_async16(dstb + tid * 16, src + tid * 4);
        cp_async16(dstb + (tid + 512) * 16, src + (tid + 512) * 4);
        if (tid < 256) cp_async16(dstb + (tid + 1024) * 16, src + (tid + 1024) * 4);
        cp_commit();
    };
    auto sts_a = [&](int buf) {
        uint32_t* Ad = Abuf + buf * A_U32;
#pragma unroll
        for (int it = 0; it < 2; it++) {
            int row = arow + it * 64;
            *(uint2*)&Ad[row * ST + kq * 2] =
                make_uint2(pack_h2(pa[it].x, pa[it].y), pack_h2(pa[it].z, pa[it].w));
        }
    };

    float acc[2][8][4];   // 64 regs
#pragma unroll
    for (int i = 0; i < 2; i++)
#pragma unroll
        for (int j = 0; j < 8; j++)
#pragma unroll
            for (int q = 0; q < 4; q++) acc[i][j][q] = 0.f;

    ldg_a(0);
    cp_b(0, 0);
    sts_a(0);
    cp_wait<0>();
    __syncthreads();

#pragma unroll 1
    for (int c = 0; c < 8; c++) {
        if (c < 7) { ldg_a(c + 1); cp_b(c + 1, (c + 1) & 1); }

        const uint32_t au_b = abase + (uint32_t)((c & 1) * A_U32 * 4);
        const uint32_t bu_b = bbase + (uint32_t)((c & 1) * B_U32 * 4);

#pragma unroll
        for (int ks = 0; ks < 2; ks++) {
            const uint32_t kbyte = ks * 32;
            uint32_t afr[2][4];
#pragma unroll
            for (int i = 0; i < 2; i++)
                LDSM_X4(afr[i][0], afr[i][1], afr[i][2], afr[i][3], au_b + aoff[i] + kbyte);
#pragma unroll
            for (int jp = 0; jp < 4; jp++) {
                uint32_t b00, b01, b10, b11;
                LDSM_X4(b00, b01, b10, b11, bu_b + boff[jp] + kbyte);
#pragma unroll
                for (int i = 0; i < 2; i++) {
                    mma_f16(acc[i][jp * 2], afr[i], b00, b01);
                    mma_f16(acc[i][jp * 2 + 1], afr[i], b10, b11);
                }
            }
        }
        if (c < 7) { sts_a((c + 1) & 1); cp_wait<0>(); }
        __syncthreads();
    }

    // ---- epilogue: p[row] = sum_u tanh(acc + qs[u]) * vs[u] ----
    float p[2][2];
#pragma unroll
    for (int i = 0; i < 2; i++) { p[i][0] = 0.f; p[i][1] = 0.f; }

#pragma unroll
    for (int j = 0; j < 8; j++) {
        int u0 = nw * 64 + j * 8 + 2 * tg;
        int u1 = u0 + 1;
        float q0 = qs[u0], q1 = qs[u1], v0 = vs[u0], v1 = vs[u1];
#pragma unroll
        for (int i = 0; i < 2; i++) {
            p[i][0] = fmaf(tanh_fast(acc[i][j][0] + q0), v0, p[i][0]);
            p[i][0] = fmaf(tanh_fast(acc[i][j][1] + q1), v1, p[i][0]);
            p[i][1] = fmaf(tanh_fast(acc[i][j][2] + q0), v0, p[i][1]);
            p[i][1] = fmaf(tanh_fast(acc[i][j][3] + q1), v1, p[i][1]);
        }
    }
#pragma unroll
    for (int off = 1; off < 4; off <<= 1)
#pragma unroll
        for (int i = 0; i < 2; i++) {
            p[i][0] += __shfl_xor_sync(0xffffffffu, p[i][0], off);
            p[i][1] += __shfl_xor_sync(0xffffffffu, p[i][1], off);
        }
    if (tg == 0) {
#pragma unroll
        for (int i = 0; i < 2; i++) {
            sp[(mw * 32 + i * 16 + g) * 4 + nw] = p[i][0];
            sp[(mw * 32 + i * 16 + g + 8) * 4 + nw] = p[i][1];
        }
    }
    __syncthreads();
    if (tid < A_ROWS) {
        float s = sp[tid * 4] + sp[tid * 4 + 1] + sp[tid * 4 + 2] + sp[tid * 4 + 3];
        d_score[r0 + tid] = s + Vb[0];
    }
}

// ============================================================
// Kernel 3: per-b softmax stats — single pass, online (m, sum) merge
// ============================================================
__global__ void softmax_stats_kernel() {
    int b = blockIdx.x, tid = threadIdx.x;
    __shared__ float rm[16], rs[16];

    float4 v = ((const float4*)(d_score + b * Tn))[tid];
    float m = fmaxf(fmaxf(v.x, v.y), fmaxf(v.z, v.w));
    float s = __expf(v.x - m) + __expf(v.y - m) + __expf(v.z - m) + __expf(v.w - m);

#pragma unroll
    for (int o = 16; o > 0; o >>= 1) {
        float m2 = __shfl_xor_sync(0xffffffffu, m, o);
        float s2 = __shfl_xor_sync(0xffffffffu, s, o);
        float mn = fmaxf(m, m2);
        s = s * __expf(m - mn) + s2 * __expf(m2 - mn);
        m = mn;
    }
    if ((tid & 31) == 0) { rm[tid >> 5] = m; rs[tid >> 5] = s; }
    __syncthreads();
    if (tid < 32) {
        float mm = (tid < 16) ? rm[tid] : -1e30f;
        float ss = (tid < 16) ? rs[tid] : 0.f;
#pragma unroll
        for (int o = 16; o > 0; o >>= 1) {
            float m2 = __shfl_xor_sync(0xffffffffu, mm, o);
            float s2 = __shfl_xor_sync(0xffffffffu, ss, o);
            float mn = fmaxf(mm, m2);
            ss = ss * __expf(mm - mn) + s2 * __expf(m2 - mn);
            mm = mn;
        }
        if (tid == 0) { d_maxv[b] = mm; d_den[b] = ss; }
    }
}

// ============================================================
// Kernel 4: weights + partial context (grid = B*32, 64-t chunks)
// ============================================================
__global__ void weights_ctx_kernel(const float* __restrict__ values,
                                   float* __restrict__ out) {
    int b = blockIdx.x >> 5;
    int ch = blockIdx.x & 31;
    int tid = threadIdx.x;
    __shared__ float sw[64];
    __shared__ float4 red[256];

    if (tid < 64) {
        int t = ch * 64 + tid;
        float w = __expf(d_score[b * Tn + t] - d_maxv[b]) / d_den[b];
        out[Bn * Dn + b * Tn + t] = w;
        sw[tid] = w;
    }
    __syncthreads();

    int rg = tid >> 6, dg = tid & 63;
    const float4* vp = (const float4*)(values + (size_t)(b * Tn + ch * 64 + rg * 16) * Dn) + dg;
    float4 acc = make_float4(0.f, 0.f, 0.f, 0.f);
#pragma unroll 8
    for (int tt = 0; tt < 16; tt++) {
        float w = sw[rg * 16 + tt];
        float4 v = vp[(size_t)tt * 64];
        acc.x = fmaf(w, v.x, acc.x);
        acc.y = fmaf(w, v.y, acc.y);
        acc.z = fmaf(w, v.z, acc.z);
        acc.w = fmaf(w, v.w, acc.w);
    }
    red[tid] = acc;
    __syncthreads();
    if (tid < 64) {
        float4 a = red[tid], b1 = red[64 + tid], c = red[128 + tid], d = red[192 + tid];
        a.x += b1.x + c.x + d.x;
        a.y += b1.y + c.y + d.y;
        a.z += b1.z + c.z + d.z;
        a.w += b1.w + c.w + d.w;
        ((float4*)(d_part + (b * 32 + ch) * Dn))[tid] = a;
    }
}

// ============================================================
// Kernel 5: reduce partial contexts -> context_vector
// ============================================================
__global__ void reduce_ctx_kernel(float* __restrict__ out) {
    int b = blockIdx.x >> 1, half = blockIdx.x & 1;
    int tid = threadIdx.x;
    int c8 = tid >> 5, q = tid & 31;
    __shared__ float4 red[256];
    float4 acc = make_float4(0.f, 0.f, 0.f, 0.f);
#pragma unroll
    for (int c = 0; c < 4; c++) {
        float4 v = ((const float4*)(d_part + (b * 32 + c8 * 4 + c) * Dn))[half * 32 + q];
        acc.x += v.x; acc.y += v.y; acc.z += v.z; acc.w += v.w;
    }
    red[tid] = acc;
    __syncthreads();
    if (tid < 32) {
        float4 a = red[tid];
#pragma unroll
        for (int w = 1; w < 8; w++) {
            float4 v = red[w * 32 + tid];
            a.x += v.x; a.y += v.y; a.z += v.z; a.w += v.w;
        }
        ((float4*)(out + b * Dn))[half * 32 + tid] = a;
    }
}

// ============================================================
extern "C" void kernel_launch(void* const* d_in, const int* in_sizes, int n_in,
                              void* d_out, int out_size) {
    const float* query = (const float*)d_in[0];
    const float* values = (const float*)d_in[1];
    const float* W1w = (const float*)d_in[2];
    const float* W1b = (const float*)d_in[3];
    const float* W2w = (const float*)d_in[4];
    const float* W2b = (const float*)d_in[5];
    const float* Vw  = (const float*)d_in[6];
    const float* Vb  = (const float*)d_in[7];
    float* out = (float*)d_out;

    static int smem_set = 0;
    if (!smem_set) {
        cudaFuncSetAttribute(score_kernel, cudaFuncAttributeMaxDynamicSharedMemorySize, SC_SMEM);
        smem_set = 1;
    }

    prep_kernel<<<96, 256>>>(query, W1w, W1b, W2w, W2b);
    score_kernel<<<(Bn * Tn) / A_ROWS, 512, SC_SMEM>>>(values, Vw, Vb);
    softmax_stats_kernel<<<Bn, 512>>>();
    weights_ctx_kernel<<<Bn * 32, 256>>>(values, out);
    reduce_ctx_kernel<<<Bn * 2, 256>>>(out);
}

// round 14
// speedup vs baseline: 1.0461x; 1.0461x over previous
#include <cuda_runtime.h>
#include <cuda_fp16.h>
#include <math.h>
#include <stdint.h>

#define Bn 64
#define Tn 2048
#define Dn 256
#define Un 256

// ---- scratch (device globals, no allocation) ----
__device__ float d_qp[Bn * Un];            // q_proj + W1_b + W2_b
__device__ float d_score[Bn * Tn];         // pre-softmax scores
// W2 as fp16, chunk-major, smem-image layout: [8 chunks][256 rows][20 u32]
__device__ __align__(16) uint32_t d_W2h[8 * 256 * 20];

// ================= helpers =================
__device__ __forceinline__ uint32_t smem_u32(const void* p) {
    uint32_t a;
    asm("{ .reg .u64 t; cvta.to.shared.u64 t, %1; cvt.u32.u64 %0, t; }" : "=r"(a) : "l"(p));
    return a;
}
__device__ __forceinline__ void cp_async16(uint32_t dst, const void* src) {
    asm volatile("cp.async.ca.shared.global [%0], [%1], 16;" :: "r"(dst), "l"(src) : "memory");
}
__device__ __forceinline__ void cp_commit() {
    asm volatile("cp.async.commit_group;" ::: "memory");
}
template <int N>
__device__ __forceinline__ void cp_wait() {
    asm volatile("cp.async.wait_group %0;" :: "n"(N) : "memory");
}
__device__ __forceinline__ void mma_f16(float* c, const uint32_t* a, uint32_t b0, uint32_t b1) {
    asm volatile(
        "mma.sync.aligned.m16n8k16.row.col.f32.f16.f16.f32 "
        "{%0,%1,%2,%3}, {%4,%5,%6,%7}, {%8,%9}, {%0,%1,%2,%3};"
        : "+f"(c[0]), "+f"(c[1]), "+f"(c[2]), "+f"(c[3])
        : "r"(a[0]), "r"(a[1]), "r"(a[2]), "r"(a[3]), "r"(b0), "r"(b1));
}
#define LDSM_X4(r0, r1, r2, r3, addr) \
    asm volatile("ldmatrix.sync.aligned.m8n8.x4.shared.b16 {%0,%1,%2,%3}, [%4];" \
                 : "=r"(r0), "=r"(r1), "=r"(r2), "=r"(r3) : "r"(addr))
__device__ __forceinline__ uint32_t pack_h2(float lo, float hi) {
    __half2 h = __floats2half2_rn(lo, hi);   // .x = lo
    return *(uint32_t*)&h;
}
static __device__ __forceinline__ float tanh_fast(float x) {
    float r;
    asm("tanh.approx.f32 %0, %1;" : "=f"(r) : "f"(x));
    return r;
}

// ============================================================
// Kernel 0: prep — qproj (0..63) + W2h build (64..95) + ctx zero (96..111)
// ============================================================
__global__ void prep_kernel(const float* __restrict__ query,
                            const float* __restrict__ W1w,
                            const float* __restrict__ W1b,
                            const float* __restrict__ W2w,
                            const float* __restrict__ W2b,
                            float* __restrict__ out) {
    if (blockIdx.x < 64) {
        int b = blockIdx.x, u = threadIdx.x;
        __shared__ float qs[Dn];
        qs[u] = query[b * Dn + u];
        __syncthreads();
        float acc = 0.f;
#pragma unroll 8
        for (int d = 0; d < Dn; d++) acc = fmaf(qs[d], W1w[d * Un + u], acc);
        d_qp[b * Un + u] = acc + W1b[u] + W2b[u];
    } else if (blockIdx.x < 96) {
        int id = (blockIdx.x - 64) * 256 + threadIdx.x;   // 0..8191
        int qg = id & 3;
        int urow = (id >> 2) & 255;
        int c = id >> 10;
        uint32_t w[4];
#pragma unroll
        for (int i = 0; i < 4; i++) {
            int q = qg * 4 + i;
            int k = c * 32 + 2 * q;
            w[i] = pack_h2(W2w[(size_t)k * Un + urow], W2w[(size_t)(k + 1) * Un + urow]);
        }
        *(uint4*)&d_W2h[(c * 256 + urow) * 20 + qg * 4] = make_uint4(w[0], w[1], w[2], w[3]);
    } else {
        // zero context-vector region of out (16 blocks x 256 threads x float4)
        int id = (blockIdx.x - 96) * 256 + threadIdx.x;   // 0..4095
        ((float4*)out)[id] = make_float4(0.f, 0.f, 0.f, 0.f);
    }
}

// ============================================================
// Kernel 2: fp16 mma.sync GEMM (128 x 256 x 256) + tanh + dot(Vw)
// EXACT R12: 8 warps = 2 M-groups x 4 N-groups, warp tile 64x64.
// A: fp32 LDG -> fp16 pack -> STS. B: direct cp.async of fp16 image.
// ============================================================
#define ST 20                       // uint32 stride per row (16 data + 4 pad)
#define A_ROWS 128
#define A_U32 (A_ROWS * ST)         // 2560 per buffer
#define B_U32 (256 * ST)            // 5120 per buffer
#define SC_SMEM (2 * (A_U32 + B_U32) * 4)   // 61440 B

__global__ __launch_bounds__(256, 1)
void score_kernel(const float* __restrict__ values,
                  const float* __restrict__ Vw,
                  const float* __restrict__ Vb) {
    extern __shared__ __align__(16) uint32_t su[];
    uint32_t* Abuf = su;                 // 2 x A_U32
    uint32_t* Bbuf = su + 2 * A_U32;     // 2 x B_U32
    __shared__ float qs[Un];
    __shared__ float vs[Un];
    __shared__ float sp[A_ROWS * 4];

    const int tid = threadIdx.x;
    const int wid = tid >> 5;
    const int lane = tid & 31;
    const int g = lane >> 2;
    const int tg = lane & 3;
    const int mw = wid >> 2;       // 0..1  (row half)
    const int nw = wid & 3;        // 0..3  (col quarter)
    const int r0 = blockIdx.x * A_ROWS;
    const int b = r0 >> 11;

    qs[tid] = d_qp[b * Un + tid];
    vs[tid] = Vw[tid];

    const int arow = tid >> 3;
    const int kq = tid & 7;

    const int lr = lane & 7;
    const int lh = (lane >> 3) & 1;
    const int lk = (lane >> 4) & 1;

    const uint32_t abase = smem_u32(Abuf);
    const uint32_t bbase = smem_u32(Bbuf);

    uint32_t aoff[4];
#pragma unroll
    for (int i = 0; i < 4; i++)
        aoff[i] = (uint32_t)(((mw * 64 + i * 16 + lr + lh * 8) * ST + lk * 4) * 4);
    uint32_t boff[4];
#pragma unroll
    for (int jp = 0; jp < 4; jp++)
        boff[jp] = (uint32_t)(((nw * 64 + jp * 16 + lr + lk * 8) * ST + lh * 4) * 4);

    float4 pa[4];

    auto ldg_a = [&](int c) {
        const int kc = c * 32;
        const float* agp = values + (size_t)r0 * Dn + kc + kq * 4;
#pragma unroll
        for (int it = 0; it < 4; it++)
            pa[it] = *(const float4*)(agp + (size_t)(arow + it * 32) * Dn);
    };
    auto cp_b = [&](int c, int buf) {
        const uint32_t* src = d_W2h + c * B_U32;
        uint32_t dstb = bbase + (uint32_t)(buf * B_U32 * 4);
#pragma unroll
        for (int it = 0; it < 5; it++) {
            int s = tid + it * 256;
            cp_async16(dstb + s * 16, src + s * 4);
        }
        cp_commit();
    };
    auto sts_a = [&](int buf) {
        uint32_t* Ad = Abuf + buf * A_U32;
#pragma unroll
        for (int it = 0; it < 4; it++) {
            int row = arow + it * 32;
            *(uint2*)&Ad[row * ST + kq * 2] =
                make_uint2(pack_h2(pa[it].x, pa[it].y), pack_h2(pa[it].z, pa[it].w));
        }
    };

    float acc[4][8][4];
#pragma unroll
    for (int i = 0; i < 4; i++)
#pragma unroll
        for (int j = 0; j < 8; j++)
#pragma unroll
            for (int q = 0; q < 4; q++) acc[i][j][q] = 0.f;

    ldg_a(0);
    cp_b(0, 0);
    sts_a(0);
    cp_wait<0>();
    __syncthreads();

#pragma unroll 1
    for (int c = 0; c < 8; c++) {
        if (c < 7) { ldg_a(c + 1); cp_b(c + 1, (c + 1) & 1); }

        const uint32_t au_b = abase + (uint32_t)((c & 1) * A_U32 * 4);
        const uint32_t bu_b = bbase + (uint32_t)((c & 1) * B_U32 * 4);

#pragma unroll
        for (int ks = 0; ks < 2; ks++) {
            const uint32_t kbyte = ks * 32;
            uint32_t afr[4][4];
#pragma unroll
            for (int i = 0; i < 4; i++)
                LDSM_X4(afr[i][0], afr[i][1], afr[i][2], afr[i][3], au_b + aoff[i] + kbyte);
#pragma unroll
            for (int jp = 0; jp < 4; jp++) {
                uint32_t b00, b01, b10, b11;
                LDSM_X4(b00, b01, b10, b11, bu_b + boff[jp] + kbyte);
#pragma unroll
                for (int i = 0; i < 4; i++) {
                    mma_f16(acc[i][jp * 2], afr[i], b00, b01);
                    mma_f16(acc[i][jp * 2 + 1], afr[i], b10, b11);
                }
            }
        }
        if (c < 7) { sts_a((c + 1) & 1); cp_wait<0>(); }
        __syncthreads();
    }

    // ---- epilogue: p[row] = sum_u tanh(acc + qs[u]) * vs[u] ----
    float p[4][2];
#pragma unroll
    for (int i = 0; i < 4; i++) { p[i][0] = 0.f; p[i][1] = 0.f; }

#pragma unroll
    for (int j = 0; j < 8; j++) {
        int u0 = nw * 64 + j * 8 + 2 * tg;
        int u1 = u0 + 1;
        float q0 = qs[u0], q1 = qs[u1], v0 = vs[u0], v1 = vs[u1];
#pragma unroll
        for (int i = 0; i < 4; i++) {
            p[i][0] = fmaf(tanh_fast(acc[i][j][0] + q0), v0, p[i][0]);
            p[i][0] = fmaf(tanh_fast(acc[i][j][1] + q1), v1, p[i][0]);
            p[i][1] = fmaf(tanh_fast(acc[i][j][2] + q0), v0, p[i][1]);
            p[i][1] = fmaf(tanh_fast(acc[i][j][3] + q1), v1, p[i][1]);
        }
    }
#pragma unroll
    for (int off = 1; off < 4; off <<= 1)
#pragma unroll
        for (int i = 0; i < 4; i++) {
            p[i][0] += __shfl_xor_sync(0xffffffffu, p[i][0], off);
            p[i][1] += __shfl_xor_sync(0xffffffffu, p[i][1], off);
        }
    if (tg == 0) {
#pragma unroll
        for (int i = 0; i < 4; i++) {
            sp[(mw * 64 + i * 16 + g) * 4 + nw] = p[i][0];
            sp[(mw * 64 + i * 16 + g + 8) * 4 + nw] = p[i][1];
        }
    }
    __syncthreads();
    if (tid < A_ROWS) {
        float s = sp[tid * 4] + sp[tid * 4 + 1] + sp[tid * 4 + 2] + sp[tid * 4 + 3];
        d_score[r0 + tid] = s + Vb[0];
    }
}

// ============================================================
// Kernel 4: weights + context (grid = B*32, 64-t chunks)
// Inline per-block softmax stats (scores L2-resident), context via atomics.
// ============================================================
__global__ void weights_ctx_kernel(const float* __restrict__ values,
                                   float* __restrict__ out) {
    int b = blockIdx.x >> 5;
    int ch = blockIdx.x & 31;
    int tid = threadIdx.x;
    __shared__ float sw[64];
    __shared__ float4 red[256];
    __shared__ float rm[8], rs[8];
    __shared__ float s_mv, s_den;

    // ---- inline softmax stats over this b's 2048 scores ----
    {
        const float4* sc = (const float4*)(d_score + b * Tn);
        float4 v1 = sc[tid], v2 = sc[tid + 256];
        float m = fmaxf(fmaxf(fmaxf(v1.x, v1.y), fmaxf(v1.z, v1.w)),
                        fmaxf(fmaxf(v2.x, v2.y), fmaxf(v2.z, v2.w)));
        float s = __expf(v1.x - m) + __expf(v1.y - m) + __expf(v1.z - m) + __expf(v1.w - m)
                + __expf(v2.x - m) + __expf(v2.y - m) + __expf(v2.z - m) + __expf(v2.w - m);
#pragma unroll
        for (int o = 16; o > 0; o >>= 1) {
            float m2 = __shfl_xor_sync(0xffffffffu, m, o);
            float s2 = __shfl_xor_sync(0xffffffffu, s, o);
            float mn = fmaxf(m, m2);
            s = s * __expf(m - mn) + s2 * __expf(m2 - mn);
            m = mn;
        }
        if ((tid & 31) == 0) { rm[tid >> 5] = m; rs[tid >> 5] = s; }
        __syncthreads();
        if (tid < 32) {
            float mm = (tid < 8) ? rm[tid] : -1e30f;
            float ss = (tid < 8) ? rs[tid] : 0.f;
#pragma unroll
            for (int o = 4; o > 0; o >>= 1) {
                float m2 = __shfl_xor_sync(0xffffffffu, mm, o);
                float s2 = __shfl_xor_sync(0xffffffffu, ss, o);
                float mn = fmaxf(mm, m2);
                ss = ss * __expf(mm - mn) + s2 * __expf(m2 - mn);
                mm = mn;
            }
            if (tid == 0) { s_mv = mm; s_den = ss; }
        }
        __syncthreads();
    }

    if (tid < 64) {
        int t = ch * 64 + tid;
        float w = __expf(d_score[b * Tn + t] - s_mv) / s_den;
        out[Bn * Dn + b * Tn + t] = w;
        sw[tid] = w;
    }
    __syncthreads();

    int rg = tid >> 6, dg = tid & 63;
    const float4* vp = (const float4*)(values + (size_t)(b * Tn + ch * 64 + rg * 16) * Dn) + dg;
    float4 acc = make_float4(0.f, 0.f, 0.f, 0.f);
#pragma unroll 8
    for (int tt = 0; tt < 16; tt++) {
        float w = sw[rg * 16 + tt];
        float4 v = vp[(size_t)tt * 64];
        acc.x = fmaf(w, v.x, acc.x);
        acc.y = fmaf(w, v.y, acc.y);
        acc.z = fmaf(w, v.z, acc.z);
        acc.w = fmaf(w, v.w, acc.w);
    }
    red[tid] = acc;
    __syncthreads();
    if (tid < 64) {
        float4 a = red[tid], b1 = red[64 + tid], c = red[128 + tid], d = red[192 + tid];
        a.x += b1.x + c.x + d.x;
        a.y += b1.y + c.y + d.y;
        a.z += b1.z + c.z + d.z;
        a.w += b1.w + c.w + d.w;
        float* op = out + b * Dn + tid * 4;
        atomicAdd(op + 0, a.x);
        atomicAdd(op + 1, a.y);
        atomicAdd(op + 2, a.z);
        atomicAdd(op + 3, a.w);
    }
}

// ============================================================
extern "C" void kernel_launch(void* const* d_in, const int* in_sizes, int n_in,
                              void* d_out, int out_size) {
    const float* query = (const float*)d_in[0];
    const float* values = (const float*)d_in[1];
    const float* W1w = (const float*)d_in[2];
    const float* W1b = (const float*)d_in[3];
    const float* W2w = (const float*)d_in[4];
    const float* W2b = (const float*)d_in[5];
    const float* Vw  = (const float*)d_in[6];
    const float* Vb  = (const float*)d_in[7];
    float* out = (float*)d_out;

    static int smem_set = 0;
    if (!smem_set) {
        cudaFuncSetAttribute(score_kernel, cudaFuncAttributeMaxDynamicSharedMemorySize, SC_SMEM);
        smem_set = 1;
    }

    prep_kernel<<<112, 256>>>(query, W1w, W1b, W2w, W2b, out);
    score_kernel<<<(Bn * Tn) / A_ROWS, 256, SC_SMEM>>>(values, Vw, Vb);
    weights_ctx_kernel<<<Bn * 32, 256>>>(values, out);
}

// round 15
// speedup vs baseline: 1.1246x; 1.0750x over previous
#include <cuda_runtime.h>
#include <cuda_fp16.h>
#include <math.h>
#include <stdint.h>

#define Bn 64
#define Tn 2048
#define Dn 256
#define Un 256

// ---- scratch (device globals, no allocation) ----
__device__ float d_qp[Bn * Un];            // q_proj + W1_b + W2_b
__device__ float d_score[Bn * Tn];         // pre-softmax scores
// W2 as fp16, chunk-major, smem-image layout: [8 chunks][256 rows][20 u32]
__device__ __align__(16) uint32_t d_W2h[8 * 256 * 20];

// ================= helpers =================
__device__ __forceinline__ uint32_t smem_u32(const void* p) {
    uint32_t a;
    asm("{ .reg .u64 t; cvta.to.shared.u64 t, %1; cvt.u32.u64 %0, t; }" : "=r"(a) : "l"(p));
    return a;
}
__device__ __forceinline__ void cp_async16(uint32_t dst, const void* src) {
    asm volatile("cp.async.ca.shared.global [%0], [%1], 16;" :: "r"(dst), "l"(src) : "memory");
}
__device__ __forceinline__ void cp_commit() {
    asm volatile("cp.async.commit_group;" ::: "memory");
}
template <int N>
__device__ __forceinline__ void cp_wait() {
    asm volatile("cp.async.wait_group %0;" :: "n"(N) : "memory");
}
__device__ __forceinline__ void mma_f16(float* c, const uint32_t* a, uint32_t b0, uint32_t b1) {
    asm volatile(
        "mma.sync.aligned.m16n8k16.row.col.f32.f16.f16.f32 "
        "{%0,%1,%2,%3}, {%4,%5,%6,%7}, {%8,%9}, {%0,%1,%2,%3};"
        : "+f"(c[0]), "+f"(c[1]), "+f"(c[2]), "+f"(c[3])
        : "r"(a[0]), "r"(a[1]), "r"(a[2]), "r"(a[3]), "r"(b0), "r"(b1));
}
#define LDSM_X4(r0, r1, r2, r3, addr) \
    asm volatile("ldmatrix.sync.aligned.m8n8.x4.shared.b16 {%0,%1,%2,%3}, [%4];" \
                 : "=r"(r0), "=r"(r1), "=r"(r2), "=r"(r3) : "r"(addr))
__device__ __forceinline__ uint32_t pack_h2(float lo, float hi) {
    __half2 h = __floats2half2_rn(lo, hi);   // .x = lo
    return *(uint32_t*)&h;
}
static __device__ __forceinline__ float tanh_fast(float x) {
    float r;
    asm("tanh.approx.f32 %0, %1;" : "=f"(r) : "f"(x));
    return r;
}

// ============================================================
// Kernel 0: prep — qproj (0..63) + W2h build (64..127) + ctx zero (128..143)
// ============================================================
__global__ void prep_kernel(const float* __restrict__ query,
                            const float* __restrict__ W1w,
                            const float* __restrict__ W1b,
                            const float* __restrict__ W2w,
                            const float* __restrict__ W2b,
                            float* __restrict__ out) {
    if (blockIdx.x < 64) {
        int b = blockIdx.x, u = threadIdx.x;
        __shared__ float qs[Dn];
        qs[u] = query[b * Dn + u];
        __syncthreads();
        float a0 = 0.f, a1 = 0.f, a2 = 0.f, a3 = 0.f;
#pragma unroll 8
        for (int d = 0; d < Dn; d += 4) {
            a0 = fmaf(qs[d + 0], W1w[(d + 0) * Un + u], a0);
            a1 = fmaf(qs[d + 1], W1w[(d + 1) * Un + u], a1);
            a2 = fmaf(qs[d + 2], W1w[(d + 2) * Un + u], a2);
            a3 = fmaf(qs[d + 3], W1w[(d + 3) * Un + u], a3);
        }
        d_qp[b * Un + u] = (a0 + a1) + (a2 + a3) + W1b[u] + W2b[u];
    } else if (blockIdx.x < 128) {
        // W2h build: block -> (chunk c, urow group); lane <-> consecutive urow
        int bid = blockIdx.x - 64;            // 0..63
        int c = bid >> 3, ug = bid & 7;
        int lane = threadIdx.x & 31, qi = threadIdx.x >> 5;   // qi 0..7
        int urow = ug * 32 + lane;
        int k0 = c * 32 + 4 * qi;             // covers q = 2qi, 2qi+1
        uint32_t w0 = pack_h2(W2w[(size_t)(k0 + 0) * Un + urow],
                              W2w[(size_t)(k0 + 1) * Un + urow]);
        uint32_t w1 = pack_h2(W2w[(size_t)(k0 + 2) * Un + urow],
                              W2w[(size_t)(k0 + 3) * Un + urow]);
        *(uint2*)&d_W2h[(c * 256 + urow) * 20 + 2 * qi] = make_uint2(w0, w1);
    } else {
        // zero context-vector region of out (16 blocks x 256 threads x float4)
        int id = (blockIdx.x - 128) * 256 + threadIdx.x;   // 0..4095
        ((float4*)out)[id] = make_float4(0.f, 0.f, 0.f, 0.f);
    }
}

// ============================================================
// Kernel 2: fp16 mma.sync GEMM (128 x 256 x 256) + tanh + dot(Vw)
// EXACT R12: 8 warps = 2 M-groups x 4 N-groups, warp tile 64x64.
// A: fp32 LDG -> fp16 pack -> STS. B: direct cp.async of fp16 image.
// ============================================================
#define ST 20                       // uint32 stride per row (16 data + 4 pad)
#define A_ROWS 128
#define A_U32 (A_ROWS * ST)         // 2560 per buffer
#define B_U32 (256 * ST)            // 5120 per buffer
#define SC_SMEM (2 * (A_U32 + B_U32) * 4)   // 61440 B

__global__ __launch_bounds__(256, 1)
void score_kernel(const float* __restrict__ values,
                  const float* __restrict__ Vw,
                  const float* __restrict__ Vb) {
    extern __shared__ __align__(16) uint32_t su[];
    uint32_t* Abuf = su;                 // 2 x A_U32
    uint32_t* Bbuf = su + 2 * A_U32;     // 2 x B_U32
    __shared__ float qs[Un];
    __shared__ float vs[Un];
    __shared__ float sp[A_ROWS * 4];

    const int tid = threadIdx.x;
    const int wid = tid >> 5;
    const int lane = tid & 31;
    const int g = lane >> 2;
    const int tg = lane & 3;
    const int mw = wid >> 2;       // 0..1  (row half)
    const int nw = wid & 3;        // 0..3  (col quarter)
    const int r0 = blockIdx.x * A_ROWS;
    const int b = r0 >> 11;

    qs[tid] = d_qp[b * Un + tid];
    vs[tid] = Vw[tid];

    const int arow = tid >> 3;
    const int kq = tid & 7;

    const int lr = lane & 7;
    const int lh = (lane >> 3) & 1;
    const int lk = (lane >> 4) & 1;

    const uint32_t abase = smem_u32(Abuf);
    const uint32_t bbase = smem_u32(Bbuf);

    uint32_t aoff[4];
#pragma unroll
    for (int i = 0; i < 4; i++)
        aoff[i] = (uint32_t)(((mw * 64 + i * 16 + lr + lh * 8) * ST + lk * 4) * 4);
    uint32_t boff[4];
#pragma unroll
    for (int jp = 0; jp < 4; jp++)
        boff[jp] = (uint32_t)(((nw * 64 + jp * 16 + lr + lk * 8) * ST + lh * 4) * 4);

    float4 pa[4];

    auto ldg_a = [&](int c) {
        const int kc = c * 32;
        const float* agp = values + (size_t)r0 * Dn + kc + kq * 4;
#pragma unroll
        for (int it = 0; it < 4; it++)
            pa[it] = *(const float4*)(agp + (size_t)(arow + it * 32) * Dn);
    };
    auto cp_b = [&](int c, int buf) {
        const uint32_t* src = d_W2h + c * B_U32;
        uint32_t dstb = bbase + (uint32_t)(buf * B_U32 * 4);
#pragma unroll
        for (int it = 0; it < 5; it++) {
            int s = tid + it * 256;
            cp_async16(dstb + s * 16, src + s * 4);
        }
        cp_commit();
    };
    auto sts_a = [&](int buf) {
        uint32_t* Ad = Abuf + buf * A_U32;
#pragma unroll
        for (int it = 0; it < 4; it++) {
            int row = arow + it * 32;
            *(uint2*)&Ad[row * ST + kq * 2] =
                make_uint2(pack_h2(pa[it].x, pa[it].y), pack_h2(pa[it].z, pa[it].w));
        }
    };

    float acc[4][8][4];
#pragma unroll
    for (int i = 0; i < 4; i++)
#pragma unroll
        for (int j = 0; j < 8; j++)
#pragma unroll
            for (int q = 0; q < 4; q++) acc[i][j][q] = 0.f;

    ldg_a(0);
    cp_b(0, 0);
    sts_a(0);
    cp_wait<0>();
    __syncthreads();

#pragma unroll 1
    for (int c = 0; c < 8; c++) {
        if (c < 7) { ldg_a(c + 1); cp_b(c + 1, (c + 1) & 1); }

        const uint32_t au_b = abase + (uint32_t)((c & 1) * A_U32 * 4);
        const uint32_t bu_b = bbase + (uint32_t)((c & 1) * B_U32 * 4);

#pragma unroll
        for (int ks = 0; ks < 2; ks++) {
            const uint32_t kbyte = ks * 32;
            uint32_t afr[4][4];
#pragma unroll
            for (int i = 0; i < 4; i++)
                LDSM_X4(afr[i][0], afr[i][1], afr[i][2], afr[i][3], au_b + aoff[i] + kbyte);
#pragma unroll
            for (int jp = 0; jp < 4; jp++) {
                uint32_t b00, b01, b10, b11;
                LDSM_X4(b00, b01, b10, b11, bu_b + boff[jp] + kbyte);
#pragma unroll
                for (int i = 0; i < 4; i++) {
                    mma_f16(acc[i][jp * 2], afr[i], b00, b01);
                    mma_f16(acc[i][jp * 2 + 1], afr[i], b10, b11);
                }
            }
        }
        if (c < 7) { sts_a((c + 1) & 1); cp_wait<0>(); }
        __syncthreads();
    }

    // ---- epilogue: p[row] = sum_u tanh(acc + qs[u]) * vs[u] ----
    float p[4][2];
#pragma unroll
    for (int i = 0; i < 4; i++) { p[i][0] = 0.f; p[i][1] = 0.f; }

#pragma unroll
    for (int j = 0; j < 8; j++) {
        int u0 = nw * 64 + j * 8 + 2 * tg;
        int u1 = u0 + 1;
        float q0 = qs[u0], q1 = qs[u1], v0 = vs[u0], v1 = vs[u1];
#pragma unroll
        for (int i = 0; i < 4; i++) {
            p[i][0] = fmaf(tanh_fast(acc[i][j][0] + q0), v0, p[i][0]);
            p[i][0] = fmaf(tanh_fast(acc[i][j][1] + q1), v1, p[i][0]);
            p[i][1] = fmaf(tanh_fast(acc[i][j][2] + q0), v0, p[i][1]);
            p[i][1] = fmaf(tanh_fast(acc[i][j][3] + q1), v1, p[i][1]);
        }
    }
#pragma unroll
    for (int off = 1; off < 4; off <<= 1)
#pragma unroll
        for (int i = 0; i < 4; i++) {
            p[i][0] += __shfl_xor_sync(0xffffffffu, p[i][0], off);
            p[i][1] += __shfl_xor_sync(0xffffffffu, p[i][1], off);
        }
    if (tg == 0) {
#pragma unroll
        for (int i = 0; i < 4; i++) {
            sp[(mw * 64 + i * 16 + g) * 4 + nw] = p[i][0];
            sp[(mw * 64 + i * 16 + g + 8) * 4 + nw] = p[i][1];
        }
    }
    __syncthreads();
    if (tid < A_ROWS) {
        float s = sp[tid * 4] + sp[tid * 4 + 1] + sp[tid * 4 + 2] + sp[tid * 4 + 3];
        d_score[r0 + tid] = s + Vb[0];
    }
}

// ============================================================
// Kernel 4: weights + context (grid = B*32, 64-t chunks)
// Inline per-block softmax stats (scores L2-resident), context via atomics.
// ============================================================
__global__ void weights_ctx_kernel(const float* __restrict__ values,
                                   float* __restrict__ out) {
    int b = blockIdx.x >> 5;
    int ch = blockIdx.x & 31;
    int tid = threadIdx.x;
    __shared__ float sw[64];
    __shared__ float4 red[256];
    __shared__ float rm[8], rs[8];
    __shared__ float s_mv, s_den;

    // ---- inline softmax stats over this b's 2048 scores ----
    {
        const float4* sc = (const float4*)(d_score + b * Tn);
        float4 v1 = sc[tid], v2 = sc[tid + 256];
        float m = fmaxf(fmaxf(fmaxf(v1.x, v1.y), fmaxf(v1.z, v1.w)),
                        fmaxf(fmaxf(v2.x, v2.y), fmaxf(v2.z, v2.w)));
        float s = __expf(v1.x - m) + __expf(v1.y - m) + __expf(v1.z - m) + __expf(v1.w - m)
                + __expf(v2.x - m) + __expf(v2.y - m) + __expf(v2.z - m) + __expf(v2.w - m);
#pragma unroll
        for (int o = 16; o > 0; o >>= 1) {
            float m2 = __shfl_xor_sync(0xffffffffu, m, o);
            float s2 = __shfl_xor_sync(0xffffffffu, s, o);
            float mn = fmaxf(m, m2);
            s = s * __expf(m - mn) + s2 * __expf(m2 - mn);
            m = mn;
        }
        if ((tid & 31) == 0) { rm[tid >> 5] = m; rs[tid >> 5] = s; }
        __syncthreads();
        if (tid < 32) {
            float mm = (tid < 8) ? rm[tid] : -1e30f;
            float ss = (tid < 8) ? rs[tid] : 0.f;
#pragma unroll
            for (int o = 4; o > 0; o >>= 1) {
                float m2 = __shfl_xor_sync(0xffffffffu, mm, o);
                float s2 = __shfl_xor_sync(0xffffffffu, ss, o);
                float mn = fmaxf(mm, m2);
                ss = ss * __expf(mm - mn) + s2 * __expf(m2 - mn);
                mm = mn;
            }
            if (tid == 0) { s_mv = mm; s_den = ss; }
        }
        __syncthreads();
    }

    if (tid < 64) {
        int t = ch * 64 + tid;
        float w = __expf(d_score[b * Tn + t] - s_mv) / s_den;
        out[Bn * Dn + b * Tn + t] = w;
        sw[tid] = w;
    }
    __syncthreads();

    int rg = tid >> 6, dg = tid & 63;
    const float4* vp = (const float4*)(values + (size_t)(b * Tn + ch * 64 + rg * 16) * Dn) + dg;
    float4 acc = make_float4(0.f, 0.f, 0.f, 0.f);
#pragma unroll 8
    for (int tt = 0; tt < 16; tt++) {
        float w = sw[rg * 16 + tt];
        float4 v = vp[(size_t)tt * 64];
        acc.x = fmaf(w, v.x, acc.x);
        acc.y = fmaf(w, v.y, acc.y);
        acc.z = fmaf(w, v.z, acc.z);
        acc.w = fmaf(w, v.w, acc.w);
    }
    red[tid] = acc;
    __syncthreads();
    if (tid < 64) {
        float4 a = red[tid], b1 = red[64 + tid], c = red[128 + tid], d = red[192 + tid];
        a.x += b1.x + c.x + d.x;
        a.y += b1.y + c.y + d.y;
        a.z += b1.z + c.z + d.z;
        a.w += b1.w + c.w + d.w;
        float* op = out + b * Dn + tid * 4;
        atomicAdd(op + 0, a.x);
        atomicAdd(op + 1, a.y);
        atomicAdd(op + 2, a.z);
        atomicAdd(op + 3, a.w);
    }
}

// ============================================================
extern "C" void kernel_launch(void* const* d_in, const int* in_sizes, int n_in,
                              void* d_out, int out_size) {
    const float* query = (const float*)d_in[0];
    const float* values = (const float*)d_in[1];
    const float* W1w = (const float*)d_in[2];
    const float* W1b = (const float*)d_in[3];
    const float* W2w = (const float*)d_in[4];
    const float* W2b = (const float*)d_in[5];
    const float* Vw  = (const float*)d_in[6];
    const float* Vb  = (const float*)d_in[7];
    float* out = (float*)d_out;

    static int smem_set = 0;
    if (!smem_set) {
        cudaFuncSetAttribute(score_kernel, cudaFuncAttributeMaxDynamicSharedMemorySize, SC_SMEM);
        smem_set = 1;
    }

    prep_kernel<<<144, 256>>>(query, W1w, W1b, W2w, W2b, out);
    score_kernel<<<(Bn * Tn) / A_ROWS, 256, SC_SMEM>>>(values, Vw, Vb);
    weights_ctx_kernel<<<Bn * 32, 256>>>(values, out);
}

// round 16
// speedup vs baseline: 1.1902x; 1.0583x over previous
#include <cuda_runtime.h>
#include <cuda_fp16.h>
#include <math.h>
#include <stdint.h>

#define Bn 64
#define Tn 2048
#define Dn 256
#define Un 256

// ---- scratch (device globals, no allocation) ----
__device__ float d_qp4[4 * Bn * Un];       // qproj partials: [chunk][b][u]
__device__ float d_score[Bn * Tn];         // pre-softmax scores
// W2 as fp16, chunk-major, smem-image layout: [8 chunks][256 rows][20 u32]
__device__ __align__(16) uint32_t d_W2h[8 * 256 * 20];

// ================= helpers =================
__device__ __forceinline__ uint32_t smem_u32(const void* p) {
    uint32_t a;
    asm("{ .reg .u64 t; cvta.to.shared.u64 t, %1; cvt.u32.u64 %0, t; }" : "=r"(a) : "l"(p));
    return a;
}
__device__ __forceinline__ void cp_async16(uint32_t dst, const void* src) {
    asm volatile("cp.async.ca.shared.global [%0], [%1], 16;" :: "r"(dst), "l"(src) : "memory");
}
__device__ __forceinline__ void cp_commit() {
    asm volatile("cp.async.commit_group;" ::: "memory");
}
template <int N>
__device__ __forceinline__ void cp_wait() {
    asm volatile("cp.async.wait_group %0;" :: "n"(N) : "memory");
}
__device__ __forceinline__ void mma_f16(float* c, const uint32_t* a, uint32_t b0, uint32_t b1) {
    asm volatile(
        "mma.sync.aligned.m16n8k16.row.col.f32.f16.f16.f32 "
        "{%0,%1,%2,%3}, {%4,%5,%6,%7}, {%8,%9}, {%0,%1,%2,%3};"
        : "+f"(c[0]), "+f"(c[1]), "+f"(c[2]), "+f"(c[3])
        : "r"(a[0]), "r"(a[1]), "r"(a[2]), "r"(a[3]), "r"(b0), "r"(b1));
}
#define LDSM_X4(r0, r1, r2, r3, addr) \
    asm volatile("ldmatrix.sync.aligned.m8n8.x4.shared.b16 {%0,%1,%2,%3}, [%4];" \
                 : "=r"(r0), "=r"(r1), "=r"(r2), "=r"(r3) : "r"(addr))
__device__ __forceinline__ uint32_t pack_h2(float lo, float hi) {
    __half2 h = __floats2half2_rn(lo, hi);   // .x = lo
    return *(uint32_t*)&h;
}
static __device__ __forceinline__ float tanh_fast(float x) {
    float r;
    asm("tanh.approx.f32 %0, %1;" : "=f"(r) : "f"(x));
    return r;
}

// ============================================================
// Kernel 0: prep — ALL-INDEPENDENT blocks:
//   0..255  : qproj partial (b = bid>>2, d-chunk c = bid&3, 64 d's)
//   256..319: W2h build
//   320..335: ctx-zero of out
// ============================================================
__global__ void prep_kernel(const float* __restrict__ query,
                            const float* __restrict__ W1w,
                            const float* __restrict__ W1b,
                            const float* __restrict__ W2w,
                            const float* __restrict__ W2b,
                            float* __restrict__ out) {
    if (blockIdx.x < 256) {
        int b = blockIdx.x >> 2, c = blockIdx.x & 3;
        int u = threadIdx.x;
        __shared__ float qsl[64];
        if (u < 64) qsl[u] = query[b * Dn + c * 64 + u];
        __syncthreads();
        const float* w = W1w + (c * 64) * Un + u;
        float a0 = 0.f, a1 = 0.f, a2 = 0.f, a3 = 0.f;
#pragma unroll 16
        for (int d = 0; d < 64; d += 4) {
            a0 = fmaf(qsl[d + 0], w[(d + 0) * Un], a0);
            a1 = fmaf(qsl[d + 1], w[(d + 1) * Un], a1);
            a2 = fmaf(qsl[d + 2], w[(d + 2) * Un], a2);
            a3 = fmaf(qsl[d + 3], w[(d + 3) * Un], a3);
        }
        float r = (a0 + a1) + (a2 + a3);
        if (c == 0) r += W1b[u] + W2b[u];
        d_qp4[(c * Bn + b) * Un + u] = r;
    } else if (blockIdx.x < 320) {
        // W2h build: block -> (chunk c, urow group); lane <-> consecutive urow
        int bid = blockIdx.x - 256;           // 0..63
        int c = bid >> 3, ug = bid & 7;
        int lane = threadIdx.x & 31, qi = threadIdx.x >> 5;   // qi 0..7
        int urow = ug * 32 + lane;
        int k0 = c * 32 + 4 * qi;
        uint32_t w0 = pack_h2(W2w[(size_t)(k0 + 0) * Un + urow],
                              W2w[(size_t)(k0 + 1) * Un + urow]);
        uint32_t w1 = pack_h2(W2w[(size_t)(k0 + 2) * Un + urow],
                              W2w[(size_t)(k0 + 3) * Un + urow]);
        *(uint2*)&d_W2h[(c * 256 + urow) * 20 + 2 * qi] = make_uint2(w0, w1);
    } else {
        // zero context-vector region of out (16 blocks x 256 threads x float4)
        int id = (blockIdx.x - 320) * 256 + threadIdx.x;   // 0..4095
        ((float4*)out)[id] = make_float4(0.f, 0.f, 0.f, 0.f);
    }
}

// ============================================================
// Kernel 2: fp16 mma.sync GEMM (128 x 256 x 256) + tanh + dot(Vw)
// EXACT R12 mainloop: 8 warps = 2 M-groups x 4 N-groups, warp tile 64x64.
// A: fp32 LDG -> fp16 pack -> STS. B: direct cp.async of fp16 image.
// ============================================================
#define ST 20                       // uint32 stride per row (16 data + 4 pad)
#define A_ROWS 128
#define A_U32 (A_ROWS * ST)         // 2560 per buffer
#define B_U32 (256 * ST)            // 5120 per buffer
#define SC_SMEM (2 * (A_U32 + B_U32) * 4)   // 61440 B

__global__ __launch_bounds__(256, 1)
void score_kernel(const float* __restrict__ values,
                  const float* __restrict__ Vw,
                  const float* __restrict__ Vb) {
    extern __shared__ __align__(16) uint32_t su[];
    uint32_t* Abuf = su;                 // 2 x A_U32
    uint32_t* Bbuf = su + 2 * A_U32;     // 2 x B_U32
    __shared__ float qs[Un];
    __shared__ float vs[Un];
    __shared__ float sp[A_ROWS * 4];

    const int tid = threadIdx.x;
    const int wid = tid >> 5;
    const int lane = tid & 31;
    const int g = lane >> 2;
    const int tg = lane & 3;
    const int mw = wid >> 2;       // 0..1  (row half)
    const int nw = wid & 3;        // 0..3  (col quarter)
    const int r0 = blockIdx.x * A_ROWS;
    const int b = r0 >> 11;

    qs[tid] = d_qp4[(0 * Bn + b) * Un + tid] + d_qp4[(1 * Bn + b) * Un + tid]
            + d_qp4[(2 * Bn + b) * Un + tid] + d_qp4[(3 * Bn + b) * Un + tid];
    vs[tid] = Vw[tid];

    const int arow = tid >> 3;
    const int kq = tid & 7;

    const int lr = lane & 7;
    const int lh = (lane >> 3) & 1;
    const int lk = (lane >> 4) & 1;

    const uint32_t abase = smem_u32(Abuf);
    const uint32_t bbase = smem_u32(Bbuf);

    uint32_t aoff[4];
#pragma unroll
    for (int i = 0; i < 4; i++)
        aoff[i] = (uint32_t)(((mw * 64 + i * 16 + lr + lh * 8) * ST + lk * 4) * 4);
    uint32_t boff[4];
#pragma unroll
    for (int jp = 0; jp < 4; jp++)
        boff[jp] = (uint32_t)(((nw * 64 + jp * 16 + lr + lk * 8) * ST + lh * 4) * 4);

    float4 pa[4];

    auto ldg_a = [&](int c) {
        const int kc = c * 32;
        const float* agp = values + (size_t)r0 * Dn + kc + kq * 4;
#pragma unroll
        for (int it = 0; it < 4; it++)
            pa[it] = *(const float4*)(agp + (size_t)(arow + it * 32) * Dn);
    };
    auto cp_b = [&](int c, int buf) {
        const uint32_t* src = d_W2h + c * B_U32;
        uint32_t dstb = bbase + (uint32_t)(buf * B_U32 * 4);
#pragma unroll
        for (int it = 0; it < 5; it++) {
            int s = tid + it * 256;
            cp_async16(dstb + s * 16, src + s * 4);
        }
        cp_commit();
    };
    auto sts_a = [&](int buf) {
        uint32_t* Ad = Abuf + buf * A_U32;
#pragma unroll
        for (int it = 0; it < 4; it++) {
            int row = arow + it * 32;
            *(uint2*)&Ad[row * ST + kq * 2] =
                make_uint2(pack_h2(pa[it].x, pa[it].y), pack_h2(pa[it].z, pa[it].w));
        }
    };

    float acc[4][8][4];
#pragma unroll
    for (int i = 0; i < 4; i++)
#pragma unroll
        for (int j = 0; j < 8; j++)
#pragma unroll
            for (int q = 0; q < 4; q++) acc[i][j][q] = 0.f;

    ldg_a(0);
    cp_b(0, 0);
    sts_a(0);
    cp_wait<0>();
    __syncthreads();

#pragma unroll 1
    for (int c = 0; c < 8; c++) {
        if (c < 7) { ldg_a(c + 1); cp_b(c + 1, (c + 1) & 1); }

        const uint32_t au_b = abase + (uint32_t)((c & 1) * A_U32 * 4);
        const uint32_t bu_b = bbase + (uint32_t)((c & 1) * B_U32 * 4);

#pragma unroll
        for (int ks = 0; ks < 2; ks++) {
            const uint32_t kbyte = ks * 32;
            uint32_t afr[4][4];
#pragma unroll
            for (int i = 0; i < 4; i++)
                LDSM_X4(afr[i][0], afr[i][1], afr[i][2], afr[i][3], au_b + aoff[i] + kbyte);
#pragma unroll
            for (int jp = 0; jp < 4; jp++) {
                uint32_t b00, b01, b10, b11;
                LDSM_X4(b00, b01, b10, b11, bu_b + boff[jp] + kbyte);
#pragma unroll
                for (int i = 0; i < 4; i++) {
                    mma_f16(acc[i][jp * 2], afr[i], b00, b01);
                    mma_f16(acc[i][jp * 2 + 1], afr[i], b10, b11);
                }
            }
        }
        if (c < 7) { sts_a((c + 1) & 1); cp_wait<0>(); }
        __syncthreads();
    }

    // ---- epilogue: p[row] = sum_u tanh(acc + qs[u]) * vs[u] ----
    float p[4][2];
#pragma unroll
    for (int i = 0; i < 4; i++) { p[i][0] = 0.f; p[i][1] = 0.f; }

#pragma unroll
    for (int j = 0; j < 8; j++) {
        int u0 = nw * 64 + j * 8 + 2 * tg;
        int u1 = u0 + 1;
        float q0 = qs[u0], q1 = qs[u1], v0 = vs[u0], v1 = vs[u1];
#pragma unroll
        for (int i = 0; i < 4; i++) {
            p[i][0] = fmaf(tanh_fast(acc[i][j][0] + q0), v0, p[i][0]);
            p[i][0] = fmaf(tanh_fast(acc[i][j][1] + q1), v1, p[i][0]);
            p[i][1] = fmaf(tanh_fast(acc[i][j][2] + q0), v0, p[i][1]);
            p[i][1] = fmaf(tanh_fast(acc[i][j][3] + q1), v1, p[i][1]);
        }
    }
#pragma unroll
    for (int off = 1; off < 4; off <<= 1)
#pragma unroll
        for (int i = 0; i < 4; i++) {
            p[i][0] += __shfl_xor_sync(0xffffffffu, p[i][0], off);
            p[i][1] += __shfl_xor_sync(0xffffffffu, p[i][1], off);
        }
    if (tg == 0) {
#pragma unroll
        for (int i = 0; i < 4; i++) {
            sp[(mw * 64 + i * 16 + g) * 4 + nw] = p[i][0];
            sp[(mw * 64 + i * 16 + g + 8) * 4 + nw] = p[i][1];
        }
    }
    __syncthreads();
    if (tid < A_ROWS) {
        float s = sp[tid * 4] + sp[tid * 4 + 1] + sp[tid * 4 + 2] + sp[tid * 4 + 3];
        d_score[r0 + tid] = s + Vb[0];
    }
}

// ============================================================
// Kernel 4: weights + context (grid = B*32, 64-t chunks)
// Inline per-block softmax stats (scores L2-resident), context via atomics.
// ============================================================
__global__ void weights_ctx_kernel(const float* __restrict__ values,
                                   float* __restrict__ out) {
    int b = blockIdx.x >> 5;
    int ch = blockIdx.x & 31;
    int tid = threadIdx.x;
    __shared__ float sw[64];
    __shared__ float4 red[256];
    __shared__ float rm[8], rs[8];
    __shared__ float s_mv, s_den;

    // ---- inline softmax stats over this b's 2048 scores ----
    {
        const float4* sc = (const float4*)(d_score + b * Tn);
        float4 v1 = sc[tid], v2 = sc[tid + 256];
        float m = fmaxf(fmaxf(fmaxf(v1.x, v1.y), fmaxf(v1.z, v1.w)),
                        fmaxf(fmaxf(v2.x, v2.y), fmaxf(v2.z, v2.w)));
        float s = __expf(v1.x - m) + __expf(v1.y - m) + __expf(v1.z - m) + __expf(v1.w - m)
                + __expf(v2.x - m) + __expf(v2.y - m) + __expf(v2.z - m) + __expf(v2.w - m);
#pragma unroll
        for (int o = 16; o > 0; o >>= 1) {
            float m2 = __shfl_xor_sync(0xffffffffu, m, o);
            float s2 = __shfl_xor_sync(0xffffffffu, s, o);
            float mn = fmaxf(m, m2);
            s = s * __expf(m - mn) + s2 * __expf(m2 - mn);
            m = mn;
        }
        if ((tid & 31) == 0) { rm[tid >> 5] = m; rs[tid >> 5] = s; }
        __syncthreads();
        if (tid < 32) {
            float mm = (tid < 8) ? rm[tid] : -1e30f;
            float ss = (tid < 8) ? rs[tid] : 0.f;
#pragma unroll
            for (int o = 4; o > 0; o >>= 1) {
                float m2 = __shfl_xor_sync(0xffffffffu, mm, o);
                float s2 = __shfl_xor_sync(0xffffffffu, ss, o);
                float mn = fmaxf(mm, m2);
                ss = ss * __expf(mm - mn) + s2 * __expf(m2 - mn);
                mm = mn;
            }
            if (tid == 0) { s_mv = mm; s_den = ss; }
        }
        __syncthreads();
    }

    if (tid < 64) {
        int t = ch * 64 + tid;
        float w = __expf(d_score[b * Tn + t] - s_mv) / s_den;
        out[Bn * Dn + b * Tn + t] = w;
        sw[tid] = w;
    }
    __syncthreads();

    int rg = tid >> 6, dg = tid & 63;
    const float4* vp = (const float4*)(values + (size_t)(b * Tn + ch * 64 + rg * 16) * Dn) + dg;
    float4 acc = make_float4(0.f, 0.f, 0.f, 0.f);
#pragma unroll 8
    for (int tt = 0; tt < 16; tt++) {
        float w = sw[rg * 16 + tt];
        float4 v = vp[(size_t)tt * 64];
        acc.x = fmaf(w, v.x, acc.x);
        acc.y = fmaf(w, v.y, acc.y);
        acc.z = fmaf(w, v.z, acc.z);
        acc.w = fmaf(w, v.w, acc.w);
    }
    red[tid] = acc;
    __syncthreads();
    if (tid < 64) {
        float4 a = red[tid], b1 = red[64 + tid], c = red[128 + tid], d = red[192 + tid];
        a.x += b1.x + c.x + d.x;
        a.y += b1.y + c.y + d.y;
        a.z += b1.z + c.z + d.z;
        a.w += b1.w + c.w + d.w;
        float* op = out + b * Dn + tid * 4;
        atomicAdd(op + 0, a.x);
        atomicAdd(op + 1, a.y);
        atomicAdd(op + 2, a.z);
        atomicAdd(op + 3, a.w);
    }
}

// ============================================================
extern "C" void kernel_launch(void* const* d_in, const int* in_sizes, int n_in,
                              void* d_out, int out_size) {
    const float* query = (const float*)d_in[0];
    const float* values = (const float*)d_in[1];
    const float* W1w = (const float*)d_in[2];
    const float* W1b = (const float*)d_in[3];
    const float* W2w = (const float*)d_in[4];
    const float* W2b = (const float*)d_in[5];
    const float* Vw  = (const float*)d_in[6];
    const float* Vb  = (const float*)d_in[7];
    float* out = (float*)d_out;

    static int smem_set = 0;
    if (!smem_set) {
        cudaFuncSetAttribute(score_kernel, cudaFuncAttributeMaxDynamicSharedMemorySize, SC_SMEM);
        smem_set = 1;
    }

    prep_kernel<<<336, 256>>>(query, W1w, W1b, W2w, W2b, out);
    score_kernel<<<(Bn * Tn) / A_ROWS, 256, SC_SMEM>>>(values, Vw, Vb);
    weights_ctx_kernel<<<Bn * 32, 256>>>(values, out);
}